// round 4
// baseline (speedup 1.0000x reference)
#include <cuda_runtime.h>
#include <math.h>
#include <stdint.h>

#define BATCH 8192
#define PDIM  512
#define DM    256
#define DI    512
#define DTR   16
#define DS    16
#define ADIM  64
#define XDW   48

// ---- static scratch ----
__device__ float g_X[BATCH * DM];
__device__ float g_U2[BATCH * DI];
__device__ float g_G[BATCH * DI];      // silu(z)
__device__ float g_XD[BATCH * XDW];
__device__ float g_Y[BATCH * DI];
__device__ float g_H[BATCH * DM];

__device__ __forceinline__ float cvt_tf32(float x) {
    uint32_t u;
    asm("cvt.rna.tf32.f32 %0, %1;" : "=r"(u) : "f"(x));
    return __uint_as_float(u);
}

__device__ __forceinline__ void mma_tf32(float* c, const uint32_t* a,
                                         uint32_t b0, uint32_t b1) {
    asm volatile(
        "mma.sync.aligned.m16n8k8.row.col.f32.tf32.tf32.f32 "
        "{%0,%1,%2,%3},{%4,%5,%6,%7},{%8,%9},{%0,%1,%2,%3};"
        : "+f"(c[0]), "+f"(c[1]), "+f"(c[2]), "+f"(c[3])
        : "r"(a[0]), "r"(a[1]), "r"(a[2]), "r"(a[3]), "r"(b0), "r"(b1));
}

__device__ __forceinline__ float sigmoidf_(float x) { return 1.f / (1.f + expf(-x)); }
__device__ __forceinline__ float softplusf_(float x) {
    return (x > 20.f) ? x : log1pf(expf(x));
}

// C[M,N] = A[M,K] @ W[N,K]^T, tf32 MMA. BM=128 BN=128 BK=16, 256 thr,
// warp tile 32x64 (2x8 m16n8 frags). Double-buffered smem.
// EPI: 0 plain(guard), 1 +bias, 2 in_proj fused (U2|G), 3 dual heads (mu|ls)
template <int EPI>
__global__ void __launch_bounds__(256)
gemm_tc(const float* __restrict__ A, int lda,
        const float* __restrict__ W, const float* __restrict__ bias,
        float* __restrict__ C, int ldc, int M, int N, int K,
        const float* __restrict__ aux0, const float* __restrict__ aux1,
        float* __restrict__ aux2) {
    const int BM = 128, BN = 128, BK = 16, PAD = 20;
    __shared__ float As[2][BM][PAD];
    __shared__ float Ws[2][BN][PAD];

    const int tid  = threadIdx.x;
    const int lane = tid & 31, wid = tid >> 5;
    const int wm = (wid & 3) * 32;          // 4 warps over M
    const int wn = (wid >> 2) * 64;         // 2 warps over N
    const int g = lane >> 2, t = lane & 3;
    const int bm = blockIdx.x * BM;
    const int bn = blockIdx.y * BN;

    const int ar = tid >> 2;                // 0..63
    const int ak = (tid & 3) * 4;
    const int nTiles = K / BK;

    float acc[2][8][4];
#pragma unroll
    for (int i = 0; i < 2; i++)
#pragma unroll
        for (int j = 0; j < 8; j++)
#pragma unroll
            for (int l = 0; l < 4; l++) acc[i][j][l] = 0.f;

    // W row loader (handles head-select and N guard)
    auto ldW = [&](int n, int k0) -> float4 {
        if (EPI == 3) {
            const float* p = (n < ADIM) ? (W + (size_t)n * K)
                                        : (aux0 + (size_t)(n - ADIM) * K);
            return *(const float4*)(p + k0);
        }
        if (n < N) return *(const float4*)(W + (size_t)n * K + k0);
        return make_float4(0.f, 0.f, 0.f, 0.f);
    };

    // prologue: tile 0
    {
        float4 a0 = *(const float4*)(A + (size_t)(bm + ar) * lda + ak);
        float4 a1 = *(const float4*)(A + (size_t)(bm + ar + 64) * lda + ak);
        float4 w0 = ldW(bn + ar, ak);
        float4 w1 = ldW(bn + ar + 64, ak);
        As[0][ar][ak+0]=cvt_tf32(a0.x); As[0][ar][ak+1]=cvt_tf32(a0.y);
        As[0][ar][ak+2]=cvt_tf32(a0.z); As[0][ar][ak+3]=cvt_tf32(a0.w);
        As[0][ar+64][ak+0]=cvt_tf32(a1.x); As[0][ar+64][ak+1]=cvt_tf32(a1.y);
        As[0][ar+64][ak+2]=cvt_tf32(a1.z); As[0][ar+64][ak+3]=cvt_tf32(a1.w);
        Ws[0][ar][ak+0]=cvt_tf32(w0.x); Ws[0][ar][ak+1]=cvt_tf32(w0.y);
        Ws[0][ar][ak+2]=cvt_tf32(w0.z); Ws[0][ar][ak+3]=cvt_tf32(w0.w);
        Ws[0][ar+64][ak+0]=cvt_tf32(w1.x); Ws[0][ar+64][ak+1]=cvt_tf32(w1.y);
        Ws[0][ar+64][ak+2]=cvt_tf32(w1.z); Ws[0][ar+64][ak+3]=cvt_tf32(w1.w);
    }
    __syncthreads();

    for (int kt = 0; kt < nTiles; kt++) {
        const int cur = kt & 1;
        const bool more = (kt + 1 < nTiles);
        float4 pa0, pa1, pw0, pw1;
        if (more) {
            int k0 = (kt + 1) * BK;
            pa0 = *(const float4*)(A + (size_t)(bm + ar) * lda + k0 + ak);
            pa1 = *(const float4*)(A + (size_t)(bm + ar + 64) * lda + k0 + ak);
            pw0 = ldW(bn + ar, k0 + ak);
            pw1 = ldW(bn + ar + 64, k0 + ak);
        }

#pragma unroll
        for (int ks = 0; ks < 2; ks++) {
            const int kb = ks * 8;
            uint32_t a[2][4];
#pragma unroll
            for (int mt = 0; mt < 2; mt++) {
                int row = wm + mt * 16 + g;
                a[mt][0] = __float_as_uint(As[cur][row][kb + t]);
                a[mt][1] = __float_as_uint(As[cur][row + 8][kb + t]);
                a[mt][2] = __float_as_uint(As[cur][row][kb + t + 4]);
                a[mt][3] = __float_as_uint(As[cur][row + 8][kb + t + 4]);
            }
            uint32_t b[8][2];
#pragma unroll
            for (int nt = 0; nt < 8; nt++) {
                int nc = wn + nt * 8 + g;
                b[nt][0] = __float_as_uint(Ws[cur][nc][kb + t]);
                b[nt][1] = __float_as_uint(Ws[cur][nc][kb + t + 4]);
            }
#pragma unroll
            for (int nt = 0; nt < 8; nt++) {
                mma_tf32(acc[0][nt], a[0], b[nt][0], b[nt][1]);
                mma_tf32(acc[1][nt], a[1], b[nt][0], b[nt][1]);
            }
        }

        if (more) {
            const int nxt = cur ^ 1;
            As[nxt][ar][ak+0]=cvt_tf32(pa0.x); As[nxt][ar][ak+1]=cvt_tf32(pa0.y);
            As[nxt][ar][ak+2]=cvt_tf32(pa0.z); As[nxt][ar][ak+3]=cvt_tf32(pa0.w);
            As[nxt][ar+64][ak+0]=cvt_tf32(pa1.x); As[nxt][ar+64][ak+1]=cvt_tf32(pa1.y);
            As[nxt][ar+64][ak+2]=cvt_tf32(pa1.z); As[nxt][ar+64][ak+3]=cvt_tf32(pa1.w);
            Ws[nxt][ar][ak+0]=cvt_tf32(pw0.x); Ws[nxt][ar][ak+1]=cvt_tf32(pw0.y);
            Ws[nxt][ar][ak+2]=cvt_tf32(pw0.z); Ws[nxt][ar][ak+3]=cvt_tf32(pw0.w);
            Ws[nxt][ar+64][ak+0]=cvt_tf32(pw1.x); Ws[nxt][ar+64][ak+1]=cvt_tf32(pw1.y);
            Ws[nxt][ar+64][ak+2]=cvt_tf32(pw1.z); Ws[nxt][ar+64][ak+3]=cvt_tf32(pw1.w);
        }
        __syncthreads();
    }

    // epilogue
#pragma unroll
    for (int mt = 0; mt < 2; mt++) {
#pragma unroll
        for (int nt = 0; nt < 8; nt++) {
#pragma unroll
            for (int ci = 0; ci < 4; ci++) {
                int row = bm + wm + mt * 16 + g + ((ci >= 2) ? 8 : 0);
                int col = bn + wn + nt * 8 + t * 2 + (ci & 1);
                float v = acc[mt][nt][ci];
                if (EPI == 0) {
                    if (col < N) C[(size_t)row * ldc + col] = v;
                } else if (EPI == 1) {
                    C[(size_t)row * ldc + col] = v + bias[col];
                } else if (EPI == 2) {
                    if (col < DI) {
                        float u = v * aux0[col * 4 + 3] + aux1[col];
                        C[(size_t)row * DI + col] = u * sigmoidf_(u);           // U2
                    } else {
                        aux2[(size_t)row * DI + (col - DI)] = v * sigmoidf_(v); // G
                    }
                } else { // EPI == 3: cols 0..63 mu (tanh), 64..127 log_std (clip)
                    if (col < ADIM) {
                        float h = tanhf(v + bias[col]);
                        C[(size_t)row * ADIM + col] = h;
                    } else {
                        float h = v + aux1[col - ADIM];
                        h = fminf(fmaxf(h, -5.f), 2.f);
                        aux2[(size_t)row * ADIM + (col - ADIM)] = h;
                    }
                }
            }
        }
    }
}

// Fused: delta = softplus(XD[:,:16] @ dt_proj^T + b); bc = B.C;
//        Y = U2 * (delta*bc + Dskip) * silu(z)
// 512 threads = one column each; RB2 rows per block.
#define RB2 16
__global__ void __launch_bounds__(512)
delta_ygate(const float* __restrict__ XD, const float* __restrict__ dtw,
            const float* __restrict__ dtb, const float* __restrict__ U2,
            const float* __restrict__ G, const float* __restrict__ Dskip,
            float* __restrict__ Y) {
    __shared__ float sXD[RB2][XDW];
    __shared__ float sbc[RB2];
    const int tid = threadIdx.x;
    const int r0 = blockIdx.x * RB2;

    if (tid < RB2 * 12) {
        int r = tid / 12, c4 = (tid % 12) * 4;
        *(float4*)&sXD[r][c4] = *(const float4*)&XD[(size_t)(r0 + r) * XDW + c4];
    }
    __syncthreads();
    if (tid < RB2) {
        float s = 0.f;
#pragma unroll
        for (int k = 0; k < DS; k++) s += sXD[tid][DTR + k] * sXD[tid][DTR + DS + k];
        sbc[tid] = s;
    }

    float w[DTR];
#pragma unroll
    for (int i = 0; i < 4; i++)
        *(float4*)&w[i * 4] = *(const float4*)(dtw + (size_t)tid * DTR + i * 4);
    const float bv = dtb[tid];
    const float dv = Dskip[tid];
    __syncthreads();

#pragma unroll 4
    for (int r = 0; r < RB2; r++) {
        float acc = bv;
#pragma unroll
        for (int k = 0; k < DTR; k++) acc += w[k] * sXD[r][k];
        float de = softplusf_(acc);
        size_t base = (size_t)(r0 + r) * DI;
        float u = U2[base + tid];
        float gg = G[base + tid];
        Y[base + tid] = u * (de * sbc[r] + dv) * gg;
    }
}

extern "C" void kernel_launch(void* const* d_in, const int* in_sizes, int n_in,
                              void* d_out, int out_size) {
    const float* perception = (const float*)d_in[0];
    const float* W_in       = (const float*)d_in[1];
    const float* b_in       = (const float*)d_in[2];
    const float* mu_w       = (const float*)d_in[3];
    const float* mu_b       = (const float*)d_in[4];
    const float* ls_w       = (const float*)d_in[5];
    const float* ls_b       = (const float*)d_in[6];
    const float* in_proj_w  = (const float*)d_in[7];
    const float* conv_w     = (const float*)d_in[8];
    const float* conv_b     = (const float*)d_in[9];
    const float* x_proj_w   = (const float*)d_in[10];
    const float* dt_proj_w  = (const float*)d_in[11];
    const float* dt_proj_b  = (const float*)d_in[12];
    const float* Dskip      = (const float*)d_in[14];
    const float* out_proj_w = (const float*)d_in[15];

    float* out = (float*)d_out;

    float *X, *U2, *G, *XD, *Y, *H;
    cudaGetSymbolAddress((void**)&X, g_X);
    cudaGetSymbolAddress((void**)&U2, g_U2);
    cudaGetSymbolAddress((void**)&G, g_G);
    cudaGetSymbolAddress((void**)&XD, g_XD);
    cudaGetSymbolAddress((void**)&Y, g_Y);
    cudaGetSymbolAddress((void**)&H, g_H);

    const int MB = BATCH / 128;   // 64

    // 1) X = perc @ W_in^T + b_in            [8192,256] K=512
    gemm_tc<1><<<dim3(MB, 2), 256>>>(perception, PDIM, W_in, b_in, X, DM,
                                     BATCH, DM, PDIM, nullptr, nullptr, nullptr);
    // 2) in_proj + silu-conv + silu(z)       [8192,1024] K=256 -> U2, G
    gemm_tc<2><<<dim3(MB, 8), 256>>>(X, DM, in_proj_w, nullptr, U2, DI,
                                     BATCH, 2 * DI, DM, conv_w, conv_b, G);
    // 3) XD = U2 @ x_proj^T                  [8192,48] K=512
    gemm_tc<0><<<dim3(MB, 1), 256>>>(U2, DI, x_proj_w, nullptr, XD, XDW,
                                     BATCH, XDW, DI, nullptr, nullptr, nullptr);
    // 4) delta + bc + gate -> Y              [8192,512]
    delta_ygate<<<BATCH / RB2, 512>>>(XD, dt_proj_w, dt_proj_b, U2, G, Dskip, Y);
    // 5) H = Y @ out_proj^T                  [8192,256] K=512
    gemm_tc<0><<<dim3(MB, 2), 256>>>(Y, DI, out_proj_w, nullptr, H, DM,
                                     BATCH, DM, DI, nullptr, nullptr, nullptr);
    // 6) heads combined: mu | log_std        [8192,128] K=256
    gemm_tc<3><<<dim3(MB, 1), 256>>>(H, DM, mu_w, mu_b, out, ADIM,
                                     BATCH, 128, DM, ls_w, ls_b, out + BATCH * ADIM);
    (void)in_sizes; (void)n_in; (void)out_size;
}

// round 6
// speedup vs baseline: 1.1158x; 1.1158x over previous
#include <cuda_runtime.h>
#include <math.h>
#include <stdint.h>

#define BATCH 8192
#define PDIM  512
#define DM    256
#define DI    512
#define DTR   16
#define DS    16
#define ADIM  64
#define XDW   48

// ---- static scratch ----
__device__ float g_X[BATCH * DM];
__device__ float g_U2[BATCH * DI];
__device__ float g_G[BATCH * DI];      // silu(z)
__device__ float g_XD[BATCH * XDW];
__device__ float g_Y[BATCH * DI];
__device__ float g_H[BATCH * DM];

__device__ __forceinline__ float cvt_tf32(float x) {
    uint32_t u;
    asm("cvt.rna.tf32.f32 %0, %1;" : "=r"(u) : "f"(x));
    return __uint_as_float(u);
}

__device__ __forceinline__ void mma_tf32(float* c, const uint32_t* a,
                                         uint32_t b0, uint32_t b1) {
    asm volatile(
        "mma.sync.aligned.m16n8k8.row.col.f32.tf32.tf32.f32 "
        "{%0,%1,%2,%3},{%4,%5,%6,%7},{%8,%9},{%0,%1,%2,%3};"
        : "+f"(c[0]), "+f"(c[1]), "+f"(c[2]), "+f"(c[3])
        : "r"(a[0]), "r"(a[1]), "r"(a[2]), "r"(a[3]), "r"(b0), "r"(b1));
}

// ---- fast transcendentals (MUFU-based, err ~2^-21) ----
__device__ __forceinline__ float fast_sigmoid(float x) {
    return __fdividef(1.f, 1.f + __expf(-x));
}
__device__ __forceinline__ float fast_softplus(float x) {
    return (x > 15.f) ? x : __logf(1.f + __expf(x));
}
__device__ __forceinline__ float fast_tanh(float x) {
    float e = __expf(-2.f * fabsf(x));          // e in (0,1]: divisor in [1,2], safe
    float t = __fdividef(1.f - e, 1.f + e);
    return copysignf(t, x);
}

// C[M,N] = A[M,K] @ W[N,K]^T, tf32 MMA. BM=128 BN=64 BK=16, 256 thr,
// warp tile 32x32. Double-buffered smem. (round-3 proven config)
// EPI: 0 plain(guard), 1 +bias, 2 in_proj fused (U2|G), 3 dual heads
template <int EPI>
__global__ void __launch_bounds__(256)
gemm_tc(const float* __restrict__ A, int lda,
        const float* __restrict__ W, const float* __restrict__ bias,
        float* __restrict__ C, int ldc, int M, int N, int K,
        const float* __restrict__ aux0, const float* __restrict__ aux1,
        float* __restrict__ aux2) {
    const int BM = 128, BN = 64, BK = 16, PAD = 20;
    __shared__ float As[2][BM][PAD];
    __shared__ float Ws[2][BN][PAD];

    const int tid  = threadIdx.x;
    const int lane = tid & 31, wid = tid >> 5;
    const int wm = (wid & 3) * 32, wn = (wid >> 2) * 32;
    const int g = lane >> 2, t = lane & 3;
    const int bm = blockIdx.x * BM;
    const int bn = (EPI == 3) ? 0 : blockIdx.y * BN;

    const float* Wp = W;
    const float* bp = bias;
    float* Cp = C;
    if (EPI == 3 && blockIdx.y == 1) { Wp = aux0; bp = aux1; Cp = aux2; }
    if (EPI != 3) { Wp = W; bp = bias; Cp = C; }

    const int ar0 = tid >> 2;
    const int ak  = (tid & 3) * 4;
    const int wr  = tid >> 2;
    const int nTiles = K / BK;

    float acc[2][4][4];
#pragma unroll
    for (int i = 0; i < 2; i++)
#pragma unroll
        for (int j = 0; j < 4; j++)
#pragma unroll
            for (int l = 0; l < 4; l++) acc[i][j][l] = 0.f;

    {
        float4 a0 = *(const float4*)(A + (size_t)(bm + ar0) * lda + ak);
        float4 a1 = *(const float4*)(A + (size_t)(bm + ar0 + 64) * lda + ak);
        float4 w0 = make_float4(0.f, 0.f, 0.f, 0.f);
        if (bn + wr < N) w0 = *(const float4*)(Wp + (size_t)(bn + wr) * K + ak);
        As[0][ar0][ak + 0] = cvt_tf32(a0.x); As[0][ar0][ak + 1] = cvt_tf32(a0.y);
        As[0][ar0][ak + 2] = cvt_tf32(a0.z); As[0][ar0][ak + 3] = cvt_tf32(a0.w);
        As[0][ar0 + 64][ak + 0] = cvt_tf32(a1.x); As[0][ar0 + 64][ak + 1] = cvt_tf32(a1.y);
        As[0][ar0 + 64][ak + 2] = cvt_tf32(a1.z); As[0][ar0 + 64][ak + 3] = cvt_tf32(a1.w);
        Ws[0][wr][ak + 0] = cvt_tf32(w0.x); Ws[0][wr][ak + 1] = cvt_tf32(w0.y);
        Ws[0][wr][ak + 2] = cvt_tf32(w0.z); Ws[0][wr][ak + 3] = cvt_tf32(w0.w);
    }
    __syncthreads();

    for (int kt = 0; kt < nTiles; kt++) {
        const int cur = kt & 1;
        float4 pa0, pa1, pw0;
        const bool more = (kt + 1 < nTiles);
        if (more) {
            int k0 = (kt + 1) * BK;
            pa0 = *(const float4*)(A + (size_t)(bm + ar0) * lda + k0 + ak);
            pa1 = *(const float4*)(A + (size_t)(bm + ar0 + 64) * lda + k0 + ak);
            pw0 = make_float4(0.f, 0.f, 0.f, 0.f);
            if (bn + wr < N) pw0 = *(const float4*)(Wp + (size_t)(bn + wr) * K + k0 + ak);
        }

#pragma unroll
        for (int ks = 0; ks < 2; ks++) {
            const int kb = ks * 8;
            uint32_t a[2][4];
#pragma unroll
            for (int mt = 0; mt < 2; mt++) {
                int row = wm + mt * 16 + g;
                a[mt][0] = __float_as_uint(As[cur][row][kb + t]);
                a[mt][1] = __float_as_uint(As[cur][row + 8][kb + t]);
                a[mt][2] = __float_as_uint(As[cur][row][kb + t + 4]);
                a[mt][3] = __float_as_uint(As[cur][row + 8][kb + t + 4]);
            }
#pragma unroll
            for (int nt = 0; nt < 4; nt++) {
                int nc = wn + nt * 8 + g;
                uint32_t b0 = __float_as_uint(Ws[cur][nc][kb + t]);
                uint32_t b1 = __float_as_uint(Ws[cur][nc][kb + t + 4]);
                mma_tf32(acc[0][nt], a[0], b0, b1);
                mma_tf32(acc[1][nt], a[1], b0, b1);
            }
        }

        if (more) {
            const int nxt = cur ^ 1;
            As[nxt][ar0][ak + 0] = cvt_tf32(pa0.x); As[nxt][ar0][ak + 1] = cvt_tf32(pa0.y);
            As[nxt][ar0][ak + 2] = cvt_tf32(pa0.z); As[nxt][ar0][ak + 3] = cvt_tf32(pa0.w);
            As[nxt][ar0 + 64][ak + 0] = cvt_tf32(pa1.x); As[nxt][ar0 + 64][ak + 1] = cvt_tf32(pa1.y);
            As[nxt][ar0 + 64][ak + 2] = cvt_tf32(pa1.z); As[nxt][ar0 + 64][ak + 3] = cvt_tf32(pa1.w);
            Ws[nxt][wr][ak + 0] = cvt_tf32(pw0.x); Ws[nxt][wr][ak + 1] = cvt_tf32(pw0.y);
            Ws[nxt][wr][ak + 2] = cvt_tf32(pw0.z); Ws[nxt][wr][ak + 3] = cvt_tf32(pw0.w);
        }
        __syncthreads();
    }

#pragma unroll
    for (int mt = 0; mt < 2; mt++) {
#pragma unroll
        for (int nt = 0; nt < 4; nt++) {
#pragma unroll
            for (int ci = 0; ci < 4; ci++) {
                int row = bm + wm + mt * 16 + g + ((ci >= 2) ? 8 : 0);
                int col = bn + wn + nt * 8 + t * 2 + (ci & 1);
                float v = acc[mt][nt][ci];
                if (EPI == 0) {
                    if (col < N) C[(size_t)row * ldc + col] = v;
                } else if (EPI == 1) {
                    C[(size_t)row * ldc + col] = v + bias[col];
                } else if (EPI == 2) {
                    if (col < DI) {
                        float u = v * aux0[col * 4 + 3] + aux1[col];
                        C[(size_t)row * DI + col] = u * fast_sigmoid(u);           // U2
                    } else {
                        aux2[(size_t)row * DI + (col - DI)] = v * fast_sigmoid(v); // G
                    }
                } else { // EPI == 3
                    float h = v + bp[col];
                    if (blockIdx.y == 0) h = fast_tanh(h);
                    else                 h = fminf(fmaxf(h, -5.f), 2.f);
                    Cp[(size_t)row * ADIM + col] = h;
                }
            }
        }
    }
}

// Fused: delta = softplus(XD[:,:16] @ dt_proj^T + b); bc = B.C;
//        Y = U2 * (delta*bc + Dskip) * silu(z)
#define RB2 16
__global__ void __launch_bounds__(512)
delta_ygate(const float* __restrict__ XD, const float* __restrict__ dtw,
            const float* __restrict__ dtb, const float* __restrict__ U2,
            const float* __restrict__ G, const float* __restrict__ Dskip,
            float* __restrict__ Y) {
    __shared__ float sXD[RB2][XDW];
    __shared__ float sbc[RB2];
    const int tid = threadIdx.x;
    const int r0 = blockIdx.x * RB2;

    if (tid < RB2 * 12) {
        int r = tid / 12, c4 = (tid % 12) * 4;
        *(float4*)&sXD[r][c4] = *(const float4*)&XD[(size_t)(r0 + r) * XDW + c4];
    }
    __syncthreads();
    if (tid < RB2) {
        float s = 0.f;
#pragma unroll
        for (int k = 0; k < DS; k++) s += sXD[tid][DTR + k] * sXD[tid][DTR + DS + k];
        sbc[tid] = s;
    }

    float w[DTR];
#pragma unroll
    for (int i = 0; i < 4; i++)
        *(float4*)&w[i * 4] = *(const float4*)(dtw + (size_t)tid * DTR + i * 4);
    const float bv = dtb[tid];
    const float dv = Dskip[tid];
    __syncthreads();

#pragma unroll 4
    for (int r = 0; r < RB2; r++) {
        float acc = bv;
#pragma unroll
        for (int k = 0; k < DTR; k++) acc += w[k] * sXD[r][k];
        float de = fast_softplus(acc);
        size_t base = (size_t)(r0 + r) * DI;
        float u = U2[base + tid];
        float gg = G[base + tid];
        Y[base + tid] = u * (de * sbc[r] + dv) * gg;
    }
}

extern "C" void kernel_launch(void* const* d_in, const int* in_sizes, int n_in,
                              void* d_out, int out_size) {
    const float* perception = (const float*)d_in[0];
    const float* W_in       = (const float*)d_in[1];
    const float* b_in       = (const float*)d_in[2];
    const float* mu_w       = (const float*)d_in[3];
    const float* mu_b       = (const float*)d_in[4];
    const float* ls_w       = (const float*)d_in[5];
    const float* ls_b       = (const float*)d_in[6];
    const float* in_proj_w  = (const float*)d_in[7];
    const float* conv_w     = (const float*)d_in[8];
    const float* conv_b     = (const float*)d_in[9];
    const float* x_proj_w   = (const float*)d_in[10];
    const float* dt_proj_w  = (const float*)d_in[11];
    const float* dt_proj_b  = (const float*)d_in[12];
    const float* Dskip      = (const float*)d_in[14];
    const float* out_proj_w = (const float*)d_in[15];

    float* out = (float*)d_out;

    float *X, *U2, *G, *XD, *Y, *H;
    cudaGetSymbolAddress((void**)&X, g_X);
    cudaGetSymbolAddress((void**)&U2, g_U2);
    cudaGetSymbolAddress((void**)&G, g_G);
    cudaGetSymbolAddress((void**)&XD, g_XD);
    cudaGetSymbolAddress((void**)&Y, g_Y);
    cudaGetSymbolAddress((void**)&H, g_H);

    const int MB = BATCH / 128;   // 64

    // 1) X = perc @ W_in^T + b_in            [8192,256] K=512
    gemm_tc<1><<<dim3(MB, DM / 64), 256>>>(perception, PDIM, W_in, b_in, X, DM,
                                           BATCH, DM, PDIM, nullptr, nullptr, nullptr);
    // 2) in_proj + silu-conv + silu(z)       [8192,1024] K=256 -> U2, G
    gemm_tc<2><<<dim3(MB, (2 * DI) / 64), 256>>>(X, DM, in_proj_w, nullptr, U2, DI,
                                                 BATCH, 2 * DI, DM, conv_w, conv_b, G);
    // 3) XD = U2 @ x_proj^T                  [8192,48] K=512
    gemm_tc<0><<<dim3(MB, 1), 256>>>(U2, DI, x_proj_w, nullptr, XD, XDW,
                                     BATCH, XDW, DI, nullptr, nullptr, nullptr);
    // 4) delta + bc + gate -> Y              [8192,512]
    delta_ygate<<<BATCH / RB2, 512>>>(XD, dt_proj_w, dt_proj_b, U2, G, Dskip, Y);
    // 5) H = Y @ out_proj^T                  [8192,256] K=512  (grid FIXED: 4 N-tiles)
    gemm_tc<0><<<dim3(MB, DM / 64), 256>>>(Y, DI, out_proj_w, nullptr, H, DM,
                                           BATCH, DM, DI, nullptr, nullptr, nullptr);
    // 6) heads: mu (by=0) | log_std (by=1)   [8192,64] K=256
    gemm_tc<3><<<dim3(MB, 2), 256>>>(H, DM, mu_w, mu_b, out, ADIM,
                                     BATCH, ADIM, DM, ls_w, ls_b, out + BATCH * ADIM);
    (void)in_sizes; (void)n_in; (void)out_size;
}